// round 1
// baseline (speedup 1.0000x reference)
#include <cuda_runtime.h>
#include <cuda_bf16.h>
#include <cstdint>

// ---------------------------------------------------------------------------
// PatchMerging: B=64, H=W=28, DIM=384, K=1
//   x            : (64, 785, 384) f32
//   w_reduction  : (768, 1536)    f32   (o, f) row-major
//   w_convert    : (768, 384)     f32   (o, c) row-major
//   ln_gamma     : (1536,)        f32
//   ln_beta      : (1536,)        f32
//   out          : (64, 197, 768) f32
//
// Pipeline:
//   1) gather 2x2 patch quadrants -> 1536-vec, LayerNorm -> scratch (12544,1536)
//   2) sgemm: (12544,1536) x (768,1536)^T -> rows 1..196 of each batch
//   3) cls:   (64,384) x (768,384)^T      -> row 0 of each batch
// ---------------------------------------------------------------------------

#define BATCH   64
#define LSEQ    785
#define DIM     384
#define FDIM    1536          // 4*DIM
#define ODIM    768           // 2*DIM
#define NPOS    196           // 14*14
#define MROWS   (BATCH * NPOS)   // 12544
#define OUTROWS 197

// 77 MB fp32 scratch for the normalized merged features
__device__ float g_mbuf[(size_t)MROWS * FDIM];

// ---------------------------------------------------------------------------
// Kernel 1: gather + LayerNorm.  One block per output row (12544 blocks).
// ---------------------------------------------------------------------------
__global__ __launch_bounds__(256) void ln_gather_kernel(
    const float* __restrict__ x,
    const float* __restrict__ gamma,
    const float* __restrict__ beta,
    float* __restrict__ mbuf)
{
    const int r   = blockIdx.x;            // 0..12543
    const int b   = r / NPOS;
    const int n   = r - b * NPOS;
    const int h2  = n / 14;
    const int w2  = n - h2 * 14;
    const int tid = threadIdx.x;

    const float* xb = x + (size_t)b * LSEQ * DIM;
    const int rowbase = 1 + (2 * h2) * 28 + 2 * w2;   // L index of quadrant (0,0)

    float v[6];
    float s = 0.f, ss = 0.f;

#pragma unroll
    for (int i = 0; i < 6; i++) {
        const int f = tid + i * 256;       // 0..1535
        const int q = f / DIM;             // quadrant 0..3
        const int c = f - q * DIM;
        // quadrant order: x0=(0,0) x1=(1,0) x2=(0,1) x3=(1,1)  (drow, dcol)
        const int drow = q & 1;            // q=1,3 -> +1 row
        const int dcol = q >> 1;           // q=2,3 -> +1 col
        const int L = rowbase + drow * 28 + dcol;
        const float val = xb[(size_t)L * DIM + c];
        v[i] = val;
        s  += val;
        ss += val * val;
    }

    // block reduction (8 warps)
    __shared__ float red_s[8], red_ss[8];
#pragma unroll
    for (int off = 16; off > 0; off >>= 1) {
        s  += __shfl_xor_sync(0xFFFFFFFFu, s,  off);
        ss += __shfl_xor_sync(0xFFFFFFFFu, ss, off);
    }
    const int warp = tid >> 5;
    const int lane = tid & 31;
    if (lane == 0) { red_s[warp] = s; red_ss[warp] = ss; }
    __syncthreads();
    if (warp == 0) {
        float a = (lane < 8) ? red_s[lane]  : 0.f;
        float c = (lane < 8) ? red_ss[lane] : 0.f;
#pragma unroll
        for (int off = 4; off > 0; off >>= 1) {
            a += __shfl_xor_sync(0xFFFFFFFFu, a, off);
            c += __shfl_xor_sync(0xFFFFFFFFu, c, off);
        }
        if (lane == 0) { red_s[0] = a; red_ss[0] = c; }
    }
    __syncthreads();

    const float inv  = 1.0f / (float)FDIM;
    const float mean = red_s[0] * inv;
    const float var  = red_ss[0] * inv - mean * mean;
    const float rstd = rsqrtf(var + 1e-5f);

    float* mrow = mbuf + (size_t)r * FDIM;
#pragma unroll
    for (int i = 0; i < 6; i++) {
        const int f = tid + i * 256;
        mrow[f] = (v[i] - mean) * rstd * gamma[f] + beta[f];
    }
}

// ---------------------------------------------------------------------------
// Kernel 2: sgemm  C[m,o] = sum_f A[m,f] * W[o,f]
// 128x128 block tile, BK=8, 256 threads, 8x8 register tile per thread.
// M=12544 (98 tiles), N=768 (6 tiles), K=1536 (192 steps). No bounds checks.
// Output row remap: m -> (b=m/196)*197 + 1 + m%196
// ---------------------------------------------------------------------------
__global__ __launch_bounds__(256) void gemm_red_kernel(
    const float* __restrict__ A,     // g_mbuf (MROWS, FDIM)
    const float* __restrict__ W,     // w_reduction (ODIM, FDIM)
    float* __restrict__ out)
{
    __shared__ float As[8][128];
    __shared__ float Bs[8][128];

    const int tid = threadIdx.x;
    const int m0  = blockIdx.y * 128;
    const int n0  = blockIdx.x * 128;

    // global-load assignment: thread loads one float4 of A and one of B
    const int lr = tid >> 1;            // 0..127 : row within tile
    const int lk = (tid & 1) * 4;       // 0 or 4 : k offset within BK

    const float* aptr = A + (size_t)(m0 + lr) * FDIM + lk;
    const float* bptr = W + (size_t)(n0 + lr) * FDIM + lk;

    // compute assignment
    const int tm = (tid >> 4) * 8;      // 0..120
    const int tn = (tid & 15) * 8;      // 0..120

    float acc[8][8];
#pragma unroll
    for (int i = 0; i < 8; i++)
#pragma unroll
        for (int j = 0; j < 8; j++) acc[i][j] = 0.f;

    for (int k0 = 0; k0 < FDIM; k0 += 8) {
        const float4 av = *(const float4*)(aptr + k0);
        const float4 bv = *(const float4*)(bptr + k0);
        __syncthreads();                 // previous iter's reads done
        As[lk + 0][lr] = av.x; As[lk + 1][lr] = av.y;
        As[lk + 2][lr] = av.z; As[lk + 3][lr] = av.w;
        Bs[lk + 0][lr] = bv.x; Bs[lk + 1][lr] = bv.y;
        Bs[lk + 2][lr] = bv.z; Bs[lk + 3][lr] = bv.w;
        __syncthreads();

#pragma unroll
        for (int k = 0; k < 8; k++) {
            float a[8], b[8];
            *(float4*)(a)     = *(const float4*)&As[k][tm];
            *(float4*)(a + 4) = *(const float4*)&As[k][tm + 4];
            *(float4*)(b)     = *(const float4*)&Bs[k][tn];
            *(float4*)(b + 4) = *(const float4*)&Bs[k][tn + 4];
#pragma unroll
            for (int i = 0; i < 8; i++)
#pragma unroll
                for (int j = 0; j < 8; j++)
                    acc[i][j] = fmaf(a[i], b[j], acc[i][j]);
        }
    }

#pragma unroll
    for (int i = 0; i < 8; i++) {
        const int m  = m0 + tm + i;
        const int b  = m / NPOS;
        const int nn = m - b * NPOS;
        float* op = out + ((size_t)b * OUTROWS + 1 + nn) * ODIM + n0 + tn;
        *(float4*)(op)     = *(const float4*)&acc[i][0];
        *(float4*)(op + 4) = *(const float4*)&acc[i][4];
    }
}

// ---------------------------------------------------------------------------
// Kernel 3: cls GEMM  out[b,0,o] = sum_c x[b,0,c] * w_convert[o,c]
// grid (64, 3), 256 threads: each thread one o.
// ---------------------------------------------------------------------------
__global__ __launch_bounds__(256) void cls_kernel(
    const float* __restrict__ x,
    const float* __restrict__ wc,
    float* __restrict__ out)
{
    const int b = blockIdx.x;
    const int o = blockIdx.y * 256 + threadIdx.x;

    __shared__ float xs[DIM];
    for (int i = threadIdx.x; i < DIM; i += 256)
        xs[i] = x[(size_t)b * LSEQ * DIM + i];
    __syncthreads();

    const float* w = wc + (size_t)o * DIM;
    float s = 0.f;
#pragma unroll 4
    for (int c = 0; c < DIM; c++) s = fmaf(xs[c], w[c], s);
    out[(size_t)b * OUTROWS * ODIM + o] = s;
}

// ---------------------------------------------------------------------------
extern "C" void kernel_launch(void* const* d_in, const int* in_sizes, int n_in,
                              void* d_out, int out_size)
{
    const float* x     = (const float*)d_in[0];
    const float* w_red = (const float*)d_in[1];
    const float* w_cvt = (const float*)d_in[2];
    const float* gamma = (const float*)d_in[3];
    const float* beta  = (const float*)d_in[4];
    float* out = (float*)d_out;

    float* mbuf;
    cudaGetSymbolAddress((void**)&mbuf, g_mbuf);

    ln_gather_kernel<<<MROWS, 256>>>(x, gamma, beta, mbuf);
    gemm_red_kernel<<<dim3(ODIM / 128, MROWS / 128), 256>>>(mbuf, w_red, out);
    cls_kernel<<<dim3(BATCH, ODIM / 256), 256>>>(x, w_cvt, out);
}

// round 3
// speedup vs baseline: 1.8142x; 1.8142x over previous
#include <cuda_runtime.h>
#include <cstdint>

// ---------------------------------------------------------------------------
// PatchMerging (B=64, H=W=28, DIM=384):
//   1) gather 2x2 quadrants -> 1536-vec, LayerNorm, round-to-tf32 -> g_mbuf
//   2) round w_reduction to tf32 (rne) -> g_wred
//   3) mma.sync tf32 GEMM (12544x1536) x (768x1536)^T -> rows 1..196
//   4) cls GEMM (64x384) x (768x384)^T -> row 0
// NOTE: harness PTX target is family 'sm_103' (no 'a'), so tcgen05.ld/st/wait
// are unavailable. mma.sync (sm_80 ISA) is the portable tensor path.
// ---------------------------------------------------------------------------

#define BATCH   64
#define LSEQ    785
#define DIM     384
#define FDIM    1536
#define ODIM    768
#define NPOS    196
#define MROWS   (BATCH * NPOS)   // 12544
#define OUTROWS 197

__device__ float g_mbuf[(size_t)MROWS * FDIM];
__device__ float g_wred[(size_t)ODIM * FDIM];

// ------------------------------ helpers -----------------------------------
__device__ __forceinline__ uint32_t smem_u32(const void* p) {
    uint32_t a;
    asm("{ .reg .u64 t; cvta.to.shared.u64 t, %1; cvt.u32.u64 %0, t; }"
        : "=r"(a) : "l"(p));
    return a;
}
__device__ __forceinline__ float tf32_rna(float x) {
    uint32_t r;
    asm("cvt.rna.tf32.f32 %0, %1;" : "=r"(r) : "f"(x));
    return __uint_as_float(r);
}
#define CP_ASYNC16(saddr, gptr) \
    asm volatile("cp.async.cg.shared.global [%0], [%1], 16;" :: "r"(saddr), "l"(gptr))
#define CP_COMMIT() asm volatile("cp.async.commit_group;" ::: "memory")
template <int N>
__device__ __forceinline__ void cp_wait() {
    asm volatile("cp.async.wait_group %0;" :: "n"(N) : "memory");
}

// mma.sync m16n8k8 tf32: D = A*B + D (fp32 accum)
__device__ __forceinline__ void mma_tf32(float* d, const uint32_t* a,
                                         uint32_t b0, uint32_t b1) {
    asm volatile(
        "mma.sync.aligned.m16n8k8.row.col.f32.tf32.tf32.f32 "
        "{%0,%1,%2,%3}, {%4,%5,%6,%7}, {%8,%9}, {%0,%1,%2,%3};"
        : "+f"(d[0]), "+f"(d[1]), "+f"(d[2]), "+f"(d[3])
        : "r"(a[0]), "r"(a[1]), "r"(a[2]), "r"(a[3]), "r"(b0), "r"(b1));
}

// ---------------------------------------------------------------------------
// Kernel 1: gather + LayerNorm (+ tf32 rne rounding on write)
// ---------------------------------------------------------------------------
__global__ __launch_bounds__(256) void ln_gather_kernel(
    const float* __restrict__ x,
    const float* __restrict__ gamma,
    const float* __restrict__ beta,
    float* __restrict__ mbuf)
{
    const int r   = blockIdx.x;
    const int b   = r / NPOS;
    const int n   = r - b * NPOS;
    const int h2  = n / 14;
    const int w2  = n - h2 * 14;
    const int tid = threadIdx.x;

    const float* xb = x + (size_t)b * LSEQ * DIM;
    const int rowbase = 1 + (2 * h2) * 28 + 2 * w2;

    float v[6];
    float s = 0.f, ss = 0.f;
#pragma unroll
    for (int i = 0; i < 6; i++) {
        const int f = tid + i * 256;
        const int q = f / DIM;
        const int c = f - q * DIM;
        const int drow = q & 1;
        const int dcol = q >> 1;
        const int L = rowbase + drow * 28 + dcol;
        const float val = xb[(size_t)L * DIM + c];
        v[i] = val;
        s  += val;
        ss += val * val;
    }

    __shared__ float red_s[8], red_ss[8];
#pragma unroll
    for (int off = 16; off > 0; off >>= 1) {
        s  += __shfl_xor_sync(0xFFFFFFFFu, s,  off);
        ss += __shfl_xor_sync(0xFFFFFFFFu, ss, off);
    }
    const int warp = tid >> 5;
    const int lane = tid & 31;
    if (lane == 0) { red_s[warp] = s; red_ss[warp] = ss; }
    __syncthreads();
    if (warp == 0) {
        float a = (lane < 8) ? red_s[lane]  : 0.f;
        float c = (lane < 8) ? red_ss[lane] : 0.f;
#pragma unroll
        for (int off = 4; off > 0; off >>= 1) {
            a += __shfl_xor_sync(0xFFFFFFFFu, a, off);
            c += __shfl_xor_sync(0xFFFFFFFFu, c, off);
        }
        if (lane == 0) { red_s[0] = a; red_ss[0] = c; }
    }
    __syncthreads();

    const float inv  = 1.0f / (float)FDIM;
    const float mean = red_s[0] * inv;
    const float var  = red_ss[0] * inv - mean * mean;
    const float rstd = rsqrtf(var + 1e-5f);

    float* mrow = mbuf + (size_t)r * FDIM;
#pragma unroll
    for (int i = 0; i < 6; i++) {
        const int f = tid + i * 256;
        mrow[f] = tf32_rna((v[i] - mean) * rstd * gamma[f] + beta[f]);
    }
}

// ---------------------------------------------------------------------------
// Kernel 1b: round w_reduction -> tf32 (rne) into g_wred
// ---------------------------------------------------------------------------
__global__ __launch_bounds__(256) void wround_kernel(const float* __restrict__ w,
                                                     float* __restrict__ wo)
{
    const int i = blockIdx.x * 256 + threadIdx.x;
    wo[i] = tf32_rna(w[i]);
}

// ---------------------------------------------------------------------------
// Kernel 2: tf32 mma.sync GEMM.
//   C[m,o] = sum_f A[m,f] * W[o,f]
//   Block 128x128x32, 256 threads (8 warps as 2(M) x 4(N), warp tile 64x32).
//   3-stage cp.async pipeline. Smem rows padded to 36 floats (16B aligned).
//   k-slot remap: mma k-slot c      <- gmem k = 2c
//                 mma k-slot c+4    <- gmem k = 2c+1
//   (valid since reduction over k is order-independent; applied to A and B)
//   => all fragment loads are contiguous 64-bit LDS.
// ---------------------------------------------------------------------------
#define BM 128
#define BN 128
#define BK 32
#define ROWF 36                              // floats per smem row (32 + pad)
#define TILE_F (128 * ROWF)                  // floats per tile (A or B)
#define STAGE_F (2 * TILE_F)                 // A + B per stage
#define NSTAGE 3
#define NCHUNK (FDIM / BK)                   // 48
#define GEMM_SMEM (NSTAGE * STAGE_F * 4)     // 110592 bytes

__global__ __launch_bounds__(256) void gemm_mma_kernel(
    const float* __restrict__ A,     // g_mbuf (MROWS, FDIM)
    const float* __restrict__ W,     // g_wred (ODIM, FDIM)
    float* __restrict__ out)
{
    extern __shared__ __align__(16) float sm[];

    const int tid  = threadIdx.x;
    const int lane = tid & 31;
    const int wid  = tid >> 5;
    const int m0 = blockIdx.y * BM;
    const int n0 = blockIdx.x * BN;
    const int wm = (wid & 1) * 64;           // warp M offset in tile
    const int wn = (wid >> 1) * 32;          // warp N offset in tile

    const float* gA = A + (size_t)m0 * FDIM;
    const float* gB = W + (size_t)n0 * FDIM;

    // global->smem load mapping: thread loads 4x16B of A and 4x16B of B
    const int lrow = tid >> 1;               // 0..127
    const int lseg = (tid & 1) * 4;          // 0 or 4 (16B segment)
    const uint32_t smbase = smem_u32(sm);

    auto load_chunk = [&](int chunk, int stage) {
        const uint32_t sA = smbase + (uint32_t)stage * (STAGE_F * 4)
                          + (uint32_t)lrow * (ROWF * 4);
        const uint32_t sB = sA + TILE_F * 4;
        const float* pA = gA + (size_t)lrow * FDIM + chunk * BK;
        const float* pB = gB + (size_t)lrow * FDIM + chunk * BK;
#pragma unroll
        for (int i = 0; i < 4; i++)
            CP_ASYNC16(sA + (lseg + i) * 16, pA + (lseg + i) * 4);
#pragma unroll
        for (int i = 0; i < 4; i++)
            CP_ASYNC16(sB + (lseg + i) * 16, pB + (lseg + i) * 4);
        CP_COMMIT();
    };

    float acc[4][4][4];
#pragma unroll
    for (int mt = 0; mt < 4; mt++)
#pragma unroll
        for (int nt = 0; nt < 4; nt++)
#pragma unroll
            for (int j = 0; j < 4; j++) acc[mt][nt][j] = 0.f;

    load_chunk(0, 0);
    load_chunk(1, 1);
    load_chunk(2, 2);
    cp_wait<2>();
    __syncthreads();

    const int g2 = lane >> 2;                // 0..7
    const int c2 = 2 * (lane & 3);           // 0,2,4,6

    for (int i = 0; i < NCHUNK; i++) {
        const int s = i % NSTAGE;
        const float* As = sm + s * STAGE_F;
        const float* Bs = As + TILE_F;

#pragma unroll
        for (int ks = 0; ks < 4; ks++) {
            uint32_t afr[4][4];
#pragma unroll
            for (int mt = 0; mt < 4; mt++) {
                const int r = wm + mt * 16 + g2;
                const float2 lo = *(const float2*)(As + r * ROWF + ks * 8 + c2);
                const float2 hi = *(const float2*)(As + (r + 8) * ROWF + ks * 8 + c2);
                afr[mt][0] = __float_as_uint(lo.x);
                afr[mt][2] = __float_as_uint(lo.y);
                afr[mt][1] = __float_as_uint(hi.x);
                afr[mt][3] = __float_as_uint(hi.y);
            }
#pragma unroll
            for (int nt = 0; nt < 4; nt++) {
                const int n = wn + nt * 8 + g2;
                const float2 bv = *(const float2*)(Bs + n * ROWF + ks * 8 + c2);
                const uint32_t b0 = __float_as_uint(bv.x);
                const uint32_t b1 = __float_as_uint(bv.y);
#pragma unroll
                for (int mt = 0; mt < 4; mt++)
                    mma_tf32(acc[mt][nt], afr[mt], b0, b1);
            }
        }

        __syncthreads();
        if (i + NSTAGE < NCHUNK) {
            load_chunk(i + NSTAGE, s);
            cp_wait<2>();
        } else {
            cp_wait<0>();
        }
        __syncthreads();
    }

    // epilogue: write with batch/row remap
#pragma unroll
    for (int mt = 0; mt < 4; mt++) {
        const int mA = m0 + wm + mt * 16 + g2;       // rows mA and mA+8
#pragma unroll
        for (int half = 0; half < 2; half++) {
            const int m  = mA + half * 8;
            const int b  = m / NPOS;
            const int nn = m - b * NPOS;
            float* orow = out + ((size_t)b * OUTROWS + 1 + nn) * ODIM + n0 + wn;
#pragma unroll
            for (int nt = 0; nt < 4; nt++) {
                float2 v;
                v.x = acc[mt][nt][2 * half + 0];
                v.y = acc[mt][nt][2 * half + 1];
                *(float2*)(orow + nt * 8 + c2) = v;
            }
        }
    }
}

// ---------------------------------------------------------------------------
// Kernel 3: cls GEMM
// ---------------------------------------------------------------------------
__global__ __launch_bounds__(256) void cls_kernel(
    const float* __restrict__ x,
    const float* __restrict__ wc,
    float* __restrict__ out)
{
    const int b = blockIdx.x;
    const int o = blockIdx.y * 256 + threadIdx.x;

    __shared__ float xs[DIM];
    for (int i = threadIdx.x; i < DIM; i += 256)
        xs[i] = x[(size_t)b * LSEQ * DIM + i];
    __syncthreads();

    const float* w = wc + (size_t)o * DIM;
    float s = 0.f;
#pragma unroll 4
    for (int c = 0; c < DIM; c++) s = fmaf(xs[c], w[c], s);
    out[(size_t)b * OUTROWS * ODIM + o] = s;
}

// ---------------------------------------------------------------------------
extern "C" void kernel_launch(void* const* d_in, const int* in_sizes, int n_in,
                              void* d_out, int out_size)
{
    const float* x     = (const float*)d_in[0];
    const float* w_red = (const float*)d_in[1];
    const float* w_cvt = (const float*)d_in[2];
    const float* gamma = (const float*)d_in[3];
    const float* beta  = (const float*)d_in[4];
    float* out = (float*)d_out;

    float* mbuf;
    float* wred;
    cudaGetSymbolAddress((void**)&mbuf, g_mbuf);
    cudaGetSymbolAddress((void**)&wred, g_wred);

    cudaFuncSetAttribute(gemm_mma_kernel,
                         cudaFuncAttributeMaxDynamicSharedMemorySize, GEMM_SMEM);

    ln_gather_kernel<<<MROWS, 256>>>(x, gamma, beta, mbuf);
    wround_kernel<<<(ODIM * FDIM) / 256, 256>>>(w_red, wred);
    gemm_mma_kernel<<<dim3(ODIM / BN, MROWS / BM), 256, GEMM_SMEM>>>(mbuf, wred, out);
    cls_kernel<<<dim3(BATCH, ODIM / 256), 256>>>(x, w_cvt, out);
}

// round 4
// speedup vs baseline: 2.3485x; 1.2945x over previous
#include <cuda_runtime.h>
#include <cstdint>

// ---------------------------------------------------------------------------
// PatchMerging (B=64, H=W=28, DIM=384):
//   1) gather 2x2 quadrants -> 1536-vec, LayerNorm, round-to-tf32 -> g_mbuf
//   2) round w_reduction to tf32 (rne) -> g_wred
//   3) mma.sync tf32 GEMM (12544x1536) x (768x1536)^T -> rows 1..196
//   4) cls GEMM (64x384) x (768x384)^T -> row 0 (warp per output)
// Harness ptxas target is family 'sm_103' (no 'a') => no tcgen05; mma.sync
// (sm_80 ISA) is the portable tensor path.
// ---------------------------------------------------------------------------

#define BATCH   64
#define LSEQ    785
#define DIM     384
#define FDIM    1536
#define ODIM    768
#define NPOS    196
#define MROWS   (BATCH * NPOS)   // 12544
#define OUTROWS 197

__device__ float g_mbuf[(size_t)MROWS * FDIM];
__device__ float g_wred[(size_t)ODIM * FDIM];

// ------------------------------ helpers -----------------------------------
__device__ __forceinline__ uint32_t smem_u32(const void* p) {
    uint32_t a;
    asm("{ .reg .u64 t; cvta.to.shared.u64 t, %1; cvt.u32.u64 %0, t; }"
        : "=r"(a) : "l"(p));
    return a;
}
__device__ __forceinline__ float tf32_rna(float x) {
    uint32_t r;
    asm("cvt.rna.tf32.f32 %0, %1;" : "=r"(r) : "f"(x));
    return __uint_as_float(r);
}
#define CP_ASYNC16(saddr, gptr) \
    asm volatile("cp.async.cg.shared.global [%0], [%1], 16;" :: "r"(saddr), "l"(gptr))
#define CP_COMMIT() asm volatile("cp.async.commit_group;" ::: "memory")
template <int N>
__device__ __forceinline__ void cp_wait() {
    asm volatile("cp.async.wait_group %0;" :: "n"(N) : "memory");
}

// mma.sync m16n8k8 tf32: D = A*B + D (fp32 accum)
__device__ __forceinline__ void mma_tf32(float* d, const uint32_t* a,
                                         uint32_t b0, uint32_t b1) {
    asm volatile(
        "mma.sync.aligned.m16n8k8.row.col.f32.tf32.tf32.f32 "
        "{%0,%1,%2,%3}, {%4,%5,%6,%7}, {%8,%9}, {%0,%1,%2,%3};"
        : "+f"(d[0]), "+f"(d[1]), "+f"(d[2]), "+f"(d[3])
        : "r"(a[0]), "r"(a[1]), "r"(a[2]), "r"(a[3]), "r"(b0), "r"(b1));
}

// ---------------------------------------------------------------------------
// Kernel 1: gather + LayerNorm (+ tf32 rne rounding on write)
// 192 threads, 2 float4 loads / thread (1536 floats per row).
// ---------------------------------------------------------------------------
__global__ __launch_bounds__(192) void ln_gather_kernel(
    const float* __restrict__ x,
    const float* __restrict__ gamma,
    const float* __restrict__ beta,
    float* __restrict__ mbuf)
{
    const int r   = blockIdx.x;
    const int b   = r / NPOS;
    const int n   = r - b * NPOS;
    const int h2  = n / 14;
    const int w2  = n - h2 * 14;
    const int tid = threadIdx.x;

    const float* xb = x + (size_t)b * LSEQ * DIM;
    const int rowbase = 1 + (2 * h2) * 28 + 2 * w2;

    float4 v[2];
    float s = 0.f, ss = 0.f;
#pragma unroll
    for (int i = 0; i < 2; i++) {
        const int f4 = tid + i * 192;       // 0..383 (float4 index)
        const int f  = f4 * 4;
        const int q  = f / DIM;             // quadrant 0..3
        const int c  = f - q * DIM;
        const int drow = q & 1;
        const int dcol = q >> 1;
        const int L = rowbase + drow * 28 + dcol;
        const float4 val = *(const float4*)(xb + (size_t)L * DIM + c);
        v[i] = val;
        s  += val.x + val.y + val.z + val.w;
        ss += val.x * val.x + val.y * val.y + val.z * val.z + val.w * val.w;
    }

    __shared__ float red_s[6], red_ss[6];
#pragma unroll
    for (int off = 16; off > 0; off >>= 1) {
        s  += __shfl_xor_sync(0xFFFFFFFFu, s,  off);
        ss += __shfl_xor_sync(0xFFFFFFFFu, ss, off);
    }
    const int warp = tid >> 5;
    const int lane = tid & 31;
    if (lane == 0) { red_s[warp] = s; red_ss[warp] = ss; }
    __syncthreads();
    if (warp == 0) {
        float a = (lane < 6) ? red_s[lane]  : 0.f;
        float c = (lane < 6) ? red_ss[lane] : 0.f;
#pragma unroll
        for (int off = 4; off > 0; off >>= 1) {
            a += __shfl_xor_sync(0xFFFFFFFFu, a, off);
            c += __shfl_xor_sync(0xFFFFFFFFu, c, off);
        }
        if (lane == 0) { red_s[0] = a; red_ss[0] = c; }
    }
    __syncthreads();

    const float inv  = 1.0f / (float)FDIM;
    const float mean = red_s[0] * inv;
    const float var  = red_ss[0] * inv - mean * mean;
    const float rstd = rsqrtf(var + 1e-5f);

    float* mrow = mbuf + (size_t)r * FDIM;
#pragma unroll
    for (int i = 0; i < 2; i++) {
        const int f4 = tid + i * 192;
        const int f  = f4 * 4;
        const float4 g = *(const float4*)(gamma + f);
        const float4 be = *(const float4*)(beta + f);
        float4 o;
        o.x = tf32_rna((v[i].x - mean) * rstd * g.x + be.x);
        o.y = tf32_rna((v[i].y - mean) * rstd * g.y + be.y);
        o.z = tf32_rna((v[i].z - mean) * rstd * g.z + be.z);
        o.w = tf32_rna((v[i].w - mean) * rstd * g.w + be.w);
        *(float4*)(mrow + f) = o;
    }
}

// ---------------------------------------------------------------------------
// Kernel 1b: round w_reduction -> tf32 (rne) into g_wred
// ---------------------------------------------------------------------------
__global__ __launch_bounds__(256) void wround_kernel(const float* __restrict__ w,
                                                     float* __restrict__ wo)
{
    const int i = blockIdx.x * 256 + threadIdx.x;
    wo[i] = tf32_rna(w[i]);
}

// ---------------------------------------------------------------------------
// Kernel 2: tf32 mma.sync GEMM.
//   Block 128x128x32, 256 threads (8 warps as 2(M) x 4(N), warp tile 64x32).
//   3-stage cp.async pipeline, ONE __syncthreads per chunk (cutlass-style:
//   the load issued at iter i targets stage (i-1)%3, whose readers finished
//   at the end-of-iter-(i-1) barrier).
// ---------------------------------------------------------------------------
#define BM 128
#define BN 128
#define BK 32
#define ROWF 36                              // floats per smem row (32 + pad)
#define TILE_F (128 * ROWF)
#define STAGE_F (2 * TILE_F)
#define NSTAGE 3
#define NCHUNK (FDIM / BK)                   // 48
#define GEMM_SMEM (NSTAGE * STAGE_F * 4)     // 110592 bytes

__global__ __launch_bounds__(256) void gemm_mma_kernel(
    const float* __restrict__ A,
    const float* __restrict__ W,
    float* __restrict__ out)
{
    extern __shared__ __align__(16) float sm[];

    const int tid  = threadIdx.x;
    const int lane = tid & 31;
    const int wid  = tid >> 5;
    const int m0 = blockIdx.y * BM;
    const int n0 = blockIdx.x * BN;
    const int wm = (wid & 1) * 64;
    const int wn = (wid >> 1) * 32;

    const float* gA = A + (size_t)m0 * FDIM;
    const float* gB = W + (size_t)n0 * FDIM;

    const int lrow = tid >> 1;
    const int lseg = (tid & 1) * 4;
    const uint32_t smbase = smem_u32(sm);

    auto load_chunk = [&](int chunk, int stage) {
        const uint32_t sA = smbase + (uint32_t)stage * (STAGE_F * 4)
                          + (uint32_t)lrow * (ROWF * 4);
        const uint32_t sB = sA + TILE_F * 4;
        const float* pA = gA + (size_t)lrow * FDIM + chunk * BK;
        const float* pB = gB + (size_t)lrow * FDIM + chunk * BK;
#pragma unroll
        for (int i = 0; i < 4; i++)
            CP_ASYNC16(sA + (lseg + i) * 16, pA + (lseg + i) * 4);
#pragma unroll
        for (int i = 0; i < 4; i++)
            CP_ASYNC16(sB + (lseg + i) * 16, pB + (lseg + i) * 4);
        CP_COMMIT();
    };

    float acc[4][4][4];
#pragma unroll
    for (int mt = 0; mt < 4; mt++)
#pragma unroll
        for (int nt = 0; nt < 4; nt++)
#pragma unroll
            for (int j = 0; j < 4; j++) acc[mt][nt][j] = 0.f;

    load_chunk(0, 0);
    load_chunk(1, 1);
    cp_wait<1>();
    __syncthreads();

    const int g2 = lane >> 2;
    const int c2 = 2 * (lane & 3);

    for (int i = 0; i < NCHUNK; i++) {
        const int ld = i + 2;
        if (ld < NCHUNK) load_chunk(ld, ld % NSTAGE);

        const int s = i % NSTAGE;
        const float* As = sm + s * STAGE_F;
        const float* Bs = As + TILE_F;

#pragma unroll
        for (int ks = 0; ks < 4; ks++) {
            uint32_t afr[4][4];
#pragma unroll
            for (int mt = 0; mt < 4; mt++) {
                const int r = wm + mt * 16 + g2;
                const float2 lo = *(const float2*)(As + r * ROWF + ks * 8 + c2);
                const float2 hi = *(const float2*)(As + (r + 8) * ROWF + ks * 8 + c2);
                afr[mt][0] = __float_as_uint(lo.x);
                afr[mt][2] = __float_as_uint(lo.y);
                afr[mt][1] = __float_as_uint(hi.x);
                afr[mt][3] = __float_as_uint(hi.y);
            }
#pragma unroll
            for (int nt = 0; nt < 4; nt++) {
                const int n = wn + nt * 8 + g2;
                const float2 bv = *(const float2*)(Bs + n * ROWF + ks * 8 + c2);
                const uint32_t b0 = __float_as_uint(bv.x);
                const uint32_t b1 = __float_as_uint(bv.y);
#pragma unroll
                for (int mt = 0; mt < 4; mt++)
                    mma_tf32(acc[mt][nt], afr[mt], b0, b1);
            }
        }

        if (ld < NCHUNK) { cp_wait<1>(); } else { cp_wait<0>(); }
        __syncthreads();
    }

    // epilogue: write with batch/row remap
#pragma unroll
    for (int mt = 0; mt < 4; mt++) {
        const int mA = m0 + wm + mt * 16 + g2;
#pragma unroll
        for (int half = 0; half < 2; half++) {
            const int m  = mA + half * 8;
            const int b  = m / NPOS;
            const int nn = m - b * NPOS;
            float* orow = out + ((size_t)b * OUTROWS + 1 + nn) * ODIM + n0 + wn;
#pragma unroll
            for (int nt = 0; nt < 4; nt++) {
                float2 v;
                v.x = acc[mt][nt][2 * half + 0];
                v.y = acc[mt][nt][2 * half + 1];
                *(float2*)(orow + nt * 8 + c2) = v;
            }
        }
    }
}

// ---------------------------------------------------------------------------
// Kernel 3: cls GEMM, warp per output element.
// idx = blockIdx.x*8 + warp; b = idx / ODIM; o = idx % ODIM.
// Lane reads 3 float4 of w row + 3 float4 of x row, fma, shuffle-reduce.
// ---------------------------------------------------------------------------
__global__ __launch_bounds__(256) void cls_kernel(
    const float* __restrict__ x,
    const float* __restrict__ wc,
    float* __restrict__ out)
{
    const int warp = threadIdx.x >> 5;
    const int lane = threadIdx.x & 31;
    const int idx  = blockIdx.x * 8 + warp;       // 0..49151
    const int b    = idx / ODIM;
    const int o    = idx - b * ODIM;

    const float4* wrow = (const float4*)(wc + (size_t)o * DIM);
    const float4* xrow = (const float4*)(x + (size_t)b * LSEQ * DIM);

    float s = 0.f;
#pragma unroll
    for (int j = 0; j < 3; j++) {
        const float4 wv = wrow[lane + 32 * j];
        const float4 xv = xrow[lane + 32 * j];
        s += wv.x * xv.x + wv.y * xv.y + wv.z * xv.z + wv.w * xv.w;
    }
#pragma unroll
    for (int off = 16; off > 0; off >>= 1)
        s += __shfl_xor_sync(0xFFFFFFFFu, s, off);

    if (lane == 0)
        out[(size_t)b * OUTROWS * ODIM + o] = s;
}

// ---------------------------------------------------------------------------
extern "C" void kernel_launch(void* const* d_in, const int* in_sizes, int n_in,
                              void* d_out, int out_size)
{
    const float* x     = (const float*)d_in[0];
    const float* w_red = (const float*)d_in[1];
    const float* w_cvt = (const float*)d_in[2];
    const float* gamma = (const float*)d_in[3];
    const float* beta  = (const float*)d_in[4];
    float* out = (float*)d_out;

    float* mbuf;
    float* wred;
    cudaGetSymbolAddress((void**)&mbuf, g_mbuf);
    cudaGetSymbolAddress((void**)&wred, g_wred);

    cudaFuncSetAttribute(gemm_mma_kernel,
                         cudaFuncAttributeMaxDynamicSharedMemorySize, GEMM_SMEM);

    ln_gather_kernel<<<MROWS, 192>>>(x, gamma, beta, mbuf);
    wround_kernel<<<(ODIM * FDIM) / 256, 256>>>(w_red, wred);
    gemm_mma_kernel<<<dim3(ODIM / BN, MROWS / BM), 256, GEMM_SMEM>>>(mbuf, wred, out);
    cls_kernel<<<(BATCH * ODIM) / 8, 256>>>(x, w_cvt, out);
}

// round 5
// speedup vs baseline: 2.5768x; 1.0972x over previous
#include <cuda_runtime.h>
#include <cstdint>

// ---------------------------------------------------------------------------
// PatchMerging (B=64, H=W=28, DIM=384):
//   1) gather 2x2 quadrants -> 1536-vec, LayerNorm, round-to-tf32 -> g_mbuf
//   2) round w_reduction to tf32 (rne) -> g_wred
//   3) mma.sync tf32 GEMM (12544x1536) x (768x1536)^T -> rows 1..196
//      tile 256x128x32, 8 warps (4Mx2N), warp tile 64x64, 4-stage cp.async
//   4) cls GEMM (64x384) x (768x384)^T -> row 0 (warp per output)
// ---------------------------------------------------------------------------

#define BATCH   64
#define LSEQ    785
#define DIM     384
#define FDIM    1536
#define ODIM    768
#define NPOS    196
#define MROWS   (BATCH * NPOS)   // 12544
#define OUTROWS 197

__device__ float g_mbuf[(size_t)MROWS * FDIM];
__device__ float g_wred[(size_t)ODIM * FDIM];

// ------------------------------ helpers -----------------------------------
__device__ __forceinline__ uint32_t smem_u32(const void* p) {
    uint32_t a;
    asm("{ .reg .u64 t; cvta.to.shared.u64 t, %1; cvt.u32.u64 %0, t; }"
        : "=r"(a) : "l"(p));
    return a;
}
__device__ __forceinline__ float tf32_rna(float x) {
    uint32_t r;
    asm("cvt.rna.tf32.f32 %0, %1;" : "=r"(r) : "f"(x));
    return __uint_as_float(r);
}
#define CP_ASYNC16(saddr, gptr) \
    asm volatile("cp.async.cg.shared.global [%0], [%1], 16;" :: "r"(saddr), "l"(gptr))
#define CP_COMMIT() asm volatile("cp.async.commit_group;" ::: "memory")
template <int N>
__device__ __forceinline__ void cp_wait() {
    asm volatile("cp.async.wait_group %0;" :: "n"(N) : "memory");
}

__device__ __forceinline__ void mma_tf32(float* d, const uint32_t* a,
                                         uint32_t b0, uint32_t b1) {
    asm volatile(
        "mma.sync.aligned.m16n8k8.row.col.f32.tf32.tf32.f32 "
        "{%0,%1,%2,%3}, {%4,%5,%6,%7}, {%8,%9}, {%0,%1,%2,%3};"
        : "+f"(d[0]), "+f"(d[1]), "+f"(d[2]), "+f"(d[3])
        : "r"(a[0]), "r"(a[1]), "r"(a[2]), "r"(a[3]), "r"(b0), "r"(b1));
}

// ---------------------------------------------------------------------------
// Kernel 1: gather + LayerNorm (+ tf32 rne rounding on write)
// ---------------------------------------------------------------------------
__global__ __launch_bounds__(192) void ln_gather_kernel(
    const float* __restrict__ x,
    const float* __restrict__ gamma,
    const float* __restrict__ beta,
    float* __restrict__ mbuf)
{
    const int r   = blockIdx.x;
    const int b   = r / NPOS;
    const int n   = r - b * NPOS;
    const int h2  = n / 14;
    const int w2  = n - h2 * 14;
    const int tid = threadIdx.x;

    const float* xb = x + (size_t)b * LSEQ * DIM;
    const int rowbase = 1 + (2 * h2) * 28 + 2 * w2;

    float4 v[2];
    float s = 0.f, ss = 0.f;
#pragma unroll
    for (int i = 0; i < 2; i++) {
        const int f4 = tid + i * 192;
        const int f  = f4 * 4;
        const int q  = f / DIM;
        const int c  = f - q * DIM;
        const int drow = q & 1;
        const int dcol = q >> 1;
        const int L = rowbase + drow * 28 + dcol;
        const float4 val = *(const float4*)(xb + (size_t)L * DIM + c);
        v[i] = val;
        s  += val.x + val.y + val.z + val.w;
        ss += val.x * val.x + val.y * val.y + val.z * val.z + val.w * val.w;
    }

    __shared__ float red_s[6], red_ss[6];
#pragma unroll
    for (int off = 16; off > 0; off >>= 1) {
        s  += __shfl_xor_sync(0xFFFFFFFFu, s,  off);
        ss += __shfl_xor_sync(0xFFFFFFFFu, ss, off);
    }
    const int warp = tid >> 5;
    const int lane = tid & 31;
    if (lane == 0) { red_s[warp] = s; red_ss[warp] = ss; }
    __syncthreads();
    if (warp == 0) {
        float a = (lane < 6) ? red_s[lane]  : 0.f;
        float c = (lane < 6) ? red_ss[lane] : 0.f;
#pragma unroll
        for (int off = 4; off > 0; off >>= 1) {
            a += __shfl_xor_sync(0xFFFFFFFFu, a, off);
            c += __shfl_xor_sync(0xFFFFFFFFu, c, off);
        }
        if (lane == 0) { red_s[0] = a; red_ss[0] = c; }
    }
    __syncthreads();

    const float inv  = 1.0f / (float)FDIM;
    const float mean = red_s[0] * inv;
    const float var  = red_ss[0] * inv - mean * mean;
    const float rstd = rsqrtf(var + 1e-5f);

    float* mrow = mbuf + (size_t)r * FDIM;
#pragma unroll
    for (int i = 0; i < 2; i++) {
        const int f4 = tid + i * 192;
        const int f  = f4 * 4;
        const float4 g = *(const float4*)(gamma + f);
        const float4 be = *(const float4*)(beta + f);
        float4 o;
        o.x = tf32_rna((v[i].x - mean) * rstd * g.x + be.x);
        o.y = tf32_rna((v[i].y - mean) * rstd * g.y + be.y);
        o.z = tf32_rna((v[i].z - mean) * rstd * g.z + be.z);
        o.w = tf32_rna((v[i].w - mean) * rstd * g.w + be.w);
        *(float4*)(mrow + f) = o;
    }
}

// ---------------------------------------------------------------------------
// Kernel 1b: round w_reduction -> tf32 (rne)
// ---------------------------------------------------------------------------
__global__ __launch_bounds__(256) void wround_kernel(const float* __restrict__ w,
                                                     float* __restrict__ wo)
{
    const int i = blockIdx.x * 256 + threadIdx.x;
    wo[i] = tf32_rna(w[i]);
}

// ---------------------------------------------------------------------------
// Kernel 2: tf32 mma.sync GEMM, 256x128x32 tile, warp tile 64x64.
// ---------------------------------------------------------------------------
#define BM 256
#define BN 128
#define BK 32
#define ROWF 36
#define A_TILE_F (BM * ROWF)                 // 9216 floats
#define B_TILE_F (BN * ROWF)                 // 4608 floats
#define STAGE_F (A_TILE_F + B_TILE_F)        // 13824 floats (55296 B)
#define NSTAGE 4
#define NCHUNK (FDIM / BK)                   // 48
#define GEMM_SMEM (NSTAGE * STAGE_F * 4)     // 221184 bytes

__global__ __launch_bounds__(256) void gemm_mma_kernel(
    const float* __restrict__ A,
    const float* __restrict__ W,
    float* __restrict__ out)
{
    extern __shared__ __align__(16) float sm[];

    const int tid  = threadIdx.x;
    const int lane = tid & 31;
    const int wid  = tid >> 5;
    const int m0 = blockIdx.y * BM;
    const int n0 = blockIdx.x * BN;
    const int wm = (wid >> 1) * 64;          // 0,64,128,192
    const int wn = (wid & 1) * 64;           // 0,64

    const float* gA = A + (size_t)m0 * FDIM;
    const float* gB = W + (size_t)n0 * FDIM;

    const int lrow = tid >> 1;               // 0..127
    const int lseg = (tid & 1) * 4;          // 0 or 4
    const uint32_t smbase = smem_u32(sm);

    auto load_chunk = [&](int chunk, int stage) {
        const uint32_t base = smbase + (uint32_t)stage * (STAGE_F * 4);
        const int koff = chunk * BK;
        // A rows lrow, lrow+128
        const float* pA0 = gA + (size_t)lrow * FDIM + koff;
        const float* pA1 = pA0 + (size_t)128 * FDIM;
        const uint32_t sA0 = base + (uint32_t)lrow * (ROWF * 4);
        const uint32_t sA1 = base + (uint32_t)(lrow + 128) * (ROWF * 4);
#pragma unroll
        for (int i = 0; i < 4; i++)
            CP_ASYNC16(sA0 + (lseg + i) * 16, pA0 + (lseg + i) * 4);
#pragma unroll
        for (int i = 0; i < 4; i++)
            CP_ASYNC16(sA1 + (lseg + i) * 16, pA1 + (lseg + i) * 4);
        // B rows lrow
        const float* pB = gB + (size_t)lrow * FDIM + koff;
        const uint32_t sB = base + (A_TILE_F * 4) + (uint32_t)lrow * (ROWF * 4);
#pragma unroll
        for (int i = 0; i < 4; i++)
            CP_ASYNC16(sB + (lseg + i) * 16, pB + (lseg + i) * 4);
        CP_COMMIT();
    };

    float acc[4][8][4];
#pragma unroll
    for (int mt = 0; mt < 4; mt++)
#pragma unroll
        for (int nt = 0; nt < 8; nt++)
#pragma unroll
            for (int j = 0; j < 4; j++) acc[mt][nt][j] = 0.f;

    load_chunk(0, 0);
    load_chunk(1, 1);
    load_chunk(2, 2);
    cp_wait<2>();
    __syncthreads();

    const int g2 = lane >> 2;                // 0..7
    const int c2 = 2 * (lane & 3);           // 0,2,4,6

    for (int i = 0; i < NCHUNK; i++) {
        const int ld = i + 3;
        if (ld < NCHUNK) load_chunk(ld, ld % NSTAGE);

        const int s = i % NSTAGE;
        const float* As = sm + s * STAGE_F;
        const float* Bs = As + A_TILE_F;

#pragma unroll
        for (int ks = 0; ks < 4; ks++) {
            uint32_t afr[4][4];
#pragma unroll
            for (int mt = 0; mt < 4; mt++) {
                const int r = wm + mt * 16 + g2;
                const float2 lo = *(const float2*)(As + r * ROWF + ks * 8 + c2);
                const float2 hi = *(const float2*)(As + (r + 8) * ROWF + ks * 8 + c2);
                afr[mt][0] = __float_as_uint(lo.x);
                afr[mt][2] = __float_as_uint(lo.y);
                afr[mt][1] = __float_as_uint(hi.x);
                afr[mt][3] = __float_as_uint(hi.y);
            }
            uint32_t bfr[8][2];
#pragma unroll
            for (int nt = 0; nt < 8; nt++) {
                const int n = wn + nt * 8 + g2;
                const float2 bv = *(const float2*)(Bs + n * ROWF + ks * 8 + c2);
                bfr[nt][0] = __float_as_uint(bv.x);
                bfr[nt][1] = __float_as_uint(bv.y);
            }
#pragma unroll
            for (int nt = 0; nt < 8; nt++)
#pragma unroll
                for (int mt = 0; mt < 4; mt++)
                    mma_tf32(acc[mt][nt], afr[mt], bfr[nt][0], bfr[nt][1]);
        }

        if (ld < NCHUNK) { cp_wait<2>(); } else { cp_wait<0>(); }
        __syncthreads();
    }

    // epilogue: write with batch/row remap
#pragma unroll
    for (int mt = 0; mt < 4; mt++) {
        const int mA = m0 + wm + mt * 16 + g2;
#pragma unroll
        for (int half = 0; half < 2; half++) {
            const int m  = mA + half * 8;
            const int b  = m / NPOS;
            const int nn = m - b * NPOS;
            float* orow = out + ((size_t)b * OUTROWS + 1 + nn) * ODIM + n0 + wn;
#pragma unroll
            for (int nt = 0; nt < 8; nt++) {
                float2 v;
                v.x = acc[mt][nt][2 * half + 0];
                v.y = acc[mt][nt][2 * half + 1];
                *(float2*)(orow + nt * 8 + c2) = v;
            }
        }
    }
}

// ---------------------------------------------------------------------------
// Kernel 3: cls GEMM, warp per output element.
// ---------------------------------------------------------------------------
__global__ __launch_bounds__(256) void cls_kernel(
    const float* __restrict__ x,
    const float* __restrict__ wc,
    float* __restrict__ out)
{
    const int warp = threadIdx.x >> 5;
    const int lane = threadIdx.x & 31;
    const int idx  = blockIdx.x * 8 + warp;
    const int b    = idx / ODIM;
    const int o    = idx - b * ODIM;

    const float4* wrow = (const float4*)(wc + (size_t)o * DIM);
    const float4* xrow = (const float4*)(x + (size_t)b * LSEQ * DIM);

    float s = 0.f;
#pragma unroll
    for (int j = 0; j < 3; j++) {
        const float4 wv = wrow[lane + 32 * j];
        const float4 xv = xrow[lane + 32 * j];
        s += wv.x * xv.x + wv.y * xv.y + wv.z * xv.z + wv.w * xv.w;
    }
#pragma unroll
    for (int off = 16; off > 0; off >>= 1)
        s += __shfl_xor_sync(0xFFFFFFFFu, s, off);

    if (lane == 0)
        out[(size_t)b * OUTROWS * ODIM + o] = s;
}

// ---------------------------------------------------------------------------
extern "C" void kernel_launch(void* const* d_in, const int* in_sizes, int n_in,
                              void* d_out, int out_size)
{
    const float* x     = (const float*)d_in[0];
    const float* w_red = (const float*)d_in[1];
    const float* w_cvt = (const float*)d_in[2];
    const float* gamma = (const float*)d_in[3];
    const float* beta  = (const float*)d_in[4];
    float* out = (float*)d_out;

    float* mbuf;
    float* wred;
    cudaGetSymbolAddress((void**)&mbuf, g_mbuf);
    cudaGetSymbolAddress((void**)&wred, g_wred);

    cudaFuncSetAttribute(gemm_mma_kernel,
                         cudaFuncAttributeMaxDynamicSharedMemorySize, GEMM_SMEM);

    ln_gather_kernel<<<MROWS, 192>>>(x, gamma, beta, mbuf);
    wround_kernel<<<(ODIM * FDIM) / 256, 256>>>(w_red, wred);
    gemm_mma_kernel<<<dim3(ODIM / BN, MROWS / BM), 256, GEMM_SMEM>>>(mbuf, wred, out);
    cls_kernel<<<(BATCH * ODIM) / 8, 256>>>(x, w_cvt, out);
}